// round 12
// baseline (speedup 1.0000x reference)
#include <cuda_runtime.h>
#include <cuda_bf16.h>
#include <cstdint>

#define LOG2E 1.4426950408889634f
#define NPTS 4096
#define NT 1024                       // 32x32 tiles of 128x128

// mma.sync m16n8k16 bf16 (row.col), f32 accum — PTX-portable tensor path.
#define MMA16816(c, a, b)                                                      \
    asm("mma.sync.aligned.m16n8k16.row.col.f32.bf16.bf16.f32 "                 \
        "{%0,%1,%2,%3}, {%4,%5,%6,%7}, {%8,%9}, {%0,%1,%2,%3};"                \
        : "+f"((c)[0]), "+f"((c)[1]), "+f"((c)[2]), "+f"((c)[3])               \
        : "r"((a)[0]), "r"((a)[1]), "r"((a)[2]), "r"((a)[3]),                  \
          "r"((b)[0]), "r"((b)[1]))

// dynamic smem byte offsets: double-buffered A/B (112B rows), CS/DS, params
#define AOFF(b)  ((b) * 28672)
#define BOFF(b)  ((b) * 28672 + 14336)
#define CSOFF(b) (57344 + (b) * 1024)
#define DSOFF(b) (57344 + (b) * 1024 + 512)
#define PRMOFF   59392
#define SMEM_REQ 59520

extern __shared__ char smem[];

__device__ __forceinline__ uint32_t pack_bf2(__nv_bfloat16 a, __nv_bfloat16 b) {
    __nv_bfloat162 t(a, b);
    return *reinterpret_cast<uint32_t*>(&t);
}

// Persistent-CTA RBF: cov[i,j] = exp2( S_ij + c_i + d_j ),
// S = 3-term bf16 split GEMM (K=48: A=[uh|ul|uh], B=[vh|vh|vl]).
// Epilogue interleaved with MMA at nt-granularity so tensor/MUFU/LSU mix;
// 3 CTAs/SM for cross-warp phase overlap.
__global__ void __launch_bounds__(256, 3) rbf_mma_p(
    const float* __restrict__ x,         // [4096,16]
    const float* __restrict__ xx,        // [4096,16]
    const float* __restrict__ scale_ff,  // [16]
    const float* __restrict__ var_ff,    // scalar
    float* __restrict__ out)             // [4096,4096]
{
    const int tid  = threadIdx.x;
    const int wid  = tid >> 5;
    const int lane = tid & 31;
    float* SINV = (float*)(smem + PRMOFF);   // [16] inv-scale, [16]=log2(var)

    if (tid >= 32 && tid < 48) {
        SINV[tid - 32] = 1.0f / log1pf(__expf(scale_ff[tid - 32]));
    } else if (tid == 48) {
        SINV[16] = log2f(log1pf(__expf(var_ff[0])));
    }

    const bool is_x = (tid < 128);
    const int rowid = tid & 127;

    int t = blockIdx.x;
    float4 ra, rb, rc, rd;
    if (t < NT) {
        const int bi0 = (t >> 5) * 128, bj0 = (t & 31) * 128;
        const float4* rowp = is_x
            ? (const float4*)(x  + (size_t)(bi0 + rowid) * 16)
            : (const float4*)(xx + (size_t)(bj0 + rowid) * 16);
        ra = rowp[0]; rb = rowp[1]; rc = rowp[2]; rd = rowp[3];
    }
    __syncthreads();   // SINV ready

    const int qrow = lane >> 2;
    const int qcol = lane & 3;
    const int wr = (wid & 3) * 32;
    const int wc = (wid >> 2) * 64;

    int buf = 0;
    while (t < NT) {
        const int bi0 = (t >> 5) * 128, bj0 = (t & 31) * 128;
        const int tn = t + gridDim.x;

        // ---- convert current rows -> smem[buf] ----
        {
            float vals[16] = {ra.x, ra.y, ra.z, ra.w, rb.x, rb.y, rb.z, rb.w,
                              rc.x, rc.y, rc.z, rc.w, rd.x, rd.y, rd.z, rd.w};
            uint32_t hp[8], lp[8];
            float s2 = 0.0f;
#pragma unroll
            for (int d = 0; d < 16; d += 2) {
                float u0 = vals[d] * SINV[d];
                float u1 = vals[d + 1] * SINV[d + 1];
                s2 = fmaf(u0, u0, fmaf(u1, u1, s2));
                float w0 = is_x ? u0 : (LOG2E * u0);
                float w1 = is_x ? u1 : (LOG2E * u1);
                __nv_bfloat16 h0 = __float2bfloat16_rn(w0);
                __nv_bfloat16 h1 = __float2bfloat16_rn(w1);
                __nv_bfloat16 l0 = __float2bfloat16_rn(w0 - __bfloat162float(h0));
                __nv_bfloat16 l1 = __float2bfloat16_rn(w1 - __bfloat162float(h1));
                hp[d >> 1] = pack_bf2(h0, h1);
                lp[d >> 1] = pack_bf2(l0, l1);
            }
            uint4 H0 = make_uint4(hp[0], hp[1], hp[2], hp[3]);
            uint4 H1 = make_uint4(hp[4], hp[5], hp[6], hp[7]);
            uint4 L0 = make_uint4(lp[0], lp[1], lp[2], lp[3]);
            uint4 L1 = make_uint4(lp[4], lp[5], lp[6], lp[7]);
            if (is_x) {
                uint4* dst = (uint4*)(smem + AOFF(buf) + rowid * 112);
                dst[0] = H0; dst[1] = H1;   // k0: uh
                dst[2] = L0; dst[3] = L1;   // k1: ul
                dst[4] = H0; dst[5] = H1;   // k2: uh
                ((float*)(smem + CSOFF(buf)))[rowid] = -0.5f * LOG2E * s2;
            } else {
                uint4* dst = (uint4*)(smem + BOFF(buf) + rowid * 112);
                dst[0] = H0; dst[1] = H1;   // k0: vh
                dst[2] = H0; dst[3] = H1;   // k1: vh
                dst[4] = L0; dst[5] = L1;   // k2: vl
                ((float*)(smem + DSOFF(buf)))[rowid] =
                    -0.5f * LOG2E * s2 + SINV[16];
            }
        }

        // ---- prefetch next tile's rows (in flight over MMA+epilogue) ----
        if (tn < NT) {
            const int nbi = (tn >> 5) * 128, nbj = (tn & 31) * 128;
            const float4* rowp = is_x
                ? (const float4*)(x  + (size_t)(nbi + rowid) * 16)
                : (const float4*)(xx + (size_t)(nbj + rowid) * 16);
            ra = rowp[0]; rb = rowp[1]; rc = rowp[2]; rd = rowp[3];
        }
        __syncthreads();   // smem[buf] ready

        // ---- compute tile t from smem[buf] ----
        const uint32_t* A   = (const uint32_t*)(smem + AOFF(buf));
        const uint32_t* B   = (const uint32_t*)(smem + BOFF(buf));
        const float*    CSb = (const float*)(smem + CSOFF(buf));
        const float*    DSb = (const float*)(smem + DSOFF(buf));

        // hoist all a-fragments (3 ks x 2 mt x 4 regs = 24 regs)
        uint32_t afr[3][2][4];
#pragma unroll
        for (int ks = 0; ks < 3; ks++) {
            const int kw = ks * 8 + qcol;
#pragma unroll
            for (int mt = 0; mt < 2; mt++) {
                const int r0 = wr + mt * 16 + qrow;
                afr[ks][mt][0] = A[r0 * 28 + kw];
                afr[ks][mt][1] = A[(r0 + 8) * 28 + kw];
                afr[ks][mt][2] = A[r0 * 28 + kw + 4];
                afr[ks][mt][3] = A[(r0 + 8) * 28 + kw + 4];
            }
        }
        float ci[4];
#pragma unroll
        for (int q = 0; q < 4; q++) ci[q] = CSb[wr + qrow + 8 * q];

        // nt-interleaved: MMA(6) -> EX2(8) -> STG(4) per nt group
#pragma unroll
        for (int nt = 0; nt < 8; nt++) {
            const int jr = wc + nt * 8 + qrow;
            float2 dj = *(const float2*)&DSb[wc + nt * 8 + 2 * qcol];
            float acc[2][4];
#pragma unroll
            for (int mt = 0; mt < 2; mt++) {
                acc[mt][0] = ci[2 * mt] + dj.x;
                acc[mt][1] = ci[2 * mt] + dj.y;
                acc[mt][2] = ci[2 * mt + 1] + dj.x;
                acc[mt][3] = ci[2 * mt + 1] + dj.y;
            }
#pragma unroll
            for (int ks = 0; ks < 3; ks++) {
                const int kw = ks * 8 + qcol;
                uint32_t b[2];
                b[0] = B[jr * 28 + kw];
                b[1] = B[jr * 28 + kw + 4];
                MMA16816(acc[0], afr[ks][0], b);
                MMA16816(acc[1], afr[ks][1], b);
            }
            const int col = bj0 + wc + nt * 8 + 2 * qcol;
#pragma unroll
            for (int mt = 0; mt < 2; mt++) {
                float f0 = acc[mt][0], f1 = acc[mt][1];
                float f2 = acc[mt][2], f3 = acc[mt][3];
                asm("ex2.approx.ftz.f32 %0, %0;" : "+f"(f0));
                asm("ex2.approx.ftz.f32 %0, %0;" : "+f"(f1));
                asm("ex2.approx.ftz.f32 %0, %0;" : "+f"(f2));
                asm("ex2.approx.ftz.f32 %0, %0;" : "+f"(f3));
                const int r0 = bi0 + wr + mt * 16 + qrow;
                *(float2*)&out[(size_t)r0 * NPTS + col] = make_float2(f0, f1);
                *(float2*)&out[(size_t)(r0 + 8) * NPTS + col] =
                    make_float2(f2, f3);
            }
        }

        t = tn;
        buf ^= 1;
    }
}

extern "C" void kernel_launch(void* const* d_in, const int* in_sizes, int n_in,
                              void* d_out, int out_size) {
    const float* x        = (const float*)d_in[0];
    const float* xx       = (const float*)d_in[1];
    const float* scale_ff = (const float*)d_in[2];
    const float* var_ff   = (const float*)d_in[3];
    float* out = (float*)d_out;

    int sms = 148;
    cudaDeviceGetAttribute(&sms, cudaDevAttrMultiProcessorCount, 0);
    int grid = 3 * sms;
    if (grid > NT) grid = NT;

    cudaFuncSetAttribute(rbf_mma_p, cudaFuncAttributeMaxDynamicSharedMemorySize,
                         SMEM_REQ);
    rbf_mma_p<<<grid, 256, SMEM_REQ>>>(x, xx, scale_ff, var_ff, out);
}

// round 13
// speedup vs baseline: 1.1218x; 1.1218x over previous
#include <cuda_runtime.h>
#include <cuda_bf16.h>
#include <cstdint>

#define LOG2E 1.4426950408889634f
#define NPTS 4096
#define NT 1024                       // 32x32 tiles of 128x128

// mma.sync m16n8k16 bf16 (row.col), f32 accum.
#define MMA16816(c, a, b0v, b1v)                                               \
    asm("mma.sync.aligned.m16n8k16.row.col.f32.bf16.bf16.f32 "                 \
        "{%0,%1,%2,%3}, {%4,%5,%6,%7}, {%8,%9}, {%0,%1,%2,%3};"                \
        : "+f"((c)[0]), "+f"((c)[1]), "+f"((c)[2]), "+f"((c)[3])               \
        : "r"((a)[0]), "r"((a)[1]), "r"((a)[2]), "r"((a)[3]),                  \
          "r"(b0v), "r"(b1v))

// smem: double-buffered A/B (96B rows, K=48 dense), CS/DS, params
#define AOFF(b)  ((b) * 24576)
#define BOFF(b)  ((b) * 24576 + 12288)
#define CSOFF(b) (49152 + (b) * 1024)
#define DSOFF(b) (49152 + (b) * 1024 + 512)
#define PRMOFF   51200
#define SMEM_REQ 51328

extern __shared__ char smem[];

__device__ __forceinline__ uint32_t pack_bf2(__nv_bfloat16 a, __nv_bfloat16 b) {
    __nv_bfloat162 t(a, b);
    return *reinterpret_cast<uint32_t*>(&t);
}

// Persistent-CTA RBF: cov[i,j] = exp2( S_ij + c_i + d_j ),
// S = 3-term bf16 split GEMM (K=48: A=[uh|ul|uh], B=[vh|vh|vl]).
// B rows PERMUTED in smem (slot = k<<4|m<<3|qc<<1|e) so each lane's output
// fragment covers 4 contiguous global columns -> coalesced STG.128 (64B
// segments, half the store wavefronts). k-words pair-interleaved -> LDS.64
// fragment loads. 96B row stride = conflict-free for the quad pattern.
__global__ void __launch_bounds__(256, 2) rbf_mma_p(
    const float* __restrict__ x,         // [4096,16]
    const float* __restrict__ xx,        // [4096,16]
    const float* __restrict__ scale_ff,  // [16]
    const float* __restrict__ var_ff,    // scalar
    float* __restrict__ out)             // [4096,4096]
{
    const int tid  = threadIdx.x;
    const int wid  = tid >> 5;
    const int lane = tid & 31;
    float* SINV = (float*)(smem + PRMOFF);   // [16] inv-scale, [16]=log2(var)

    if (tid >= 32 && tid < 48) {
        SINV[tid - 32] = 1.0f / log1pf(__expf(scale_ff[tid - 32]));
    } else if (tid == 48) {
        SINV[16] = log2f(log1pf(__expf(var_ff[0])));
    }

    const bool is_x = (tid < 128);
    const int rowid = tid & 127;

    int t = blockIdx.x;
    float4 ra, rb, rc, rd;
    if (t < NT) {
        const int bi0 = (t >> 5) * 128, bj0 = (t & 31) * 128;
        const float4* rowp = is_x
            ? (const float4*)(x  + (size_t)(bi0 + rowid) * 16)
            : (const float4*)(xx + (size_t)(bj0 + rowid) * 16);
        ra = rowp[0]; rb = rowp[1]; rc = rowp[2]; rd = rowp[3];
    }
    __syncthreads();   // SINV ready

    const int qrow = lane >> 2;
    const int qcol = lane & 3;
    const int wr = (wid & 3) * 32;
    const int wc = (wid >> 2) * 64;

    int buf = 0;
    while (t < NT) {
        const int bi0 = (t >> 5) * 128, bj0 = (t & 31) * 128;
        const int tn = t + gridDim.x;

        // ---- convert current rows -> smem[buf] ----
        {
            float vals[16] = {ra.x, ra.y, ra.z, ra.w, rb.x, rb.y, rb.z, rb.w,
                              rc.x, rc.y, rc.z, rc.w, rd.x, rd.y, rd.z, rd.w};
            uint32_t hp[8], lp[8];
            float s2 = 0.0f;
#pragma unroll
            for (int d = 0; d < 16; d += 2) {
                float u0 = vals[d] * SINV[d];
                float u1 = vals[d + 1] * SINV[d + 1];
                s2 = fmaf(u0, u0, fmaf(u1, u1, s2));
                float w0 = is_x ? u0 : (LOG2E * u0);
                float w1 = is_x ? u1 : (LOG2E * u1);
                __nv_bfloat16 h0 = __float2bfloat16_rn(w0);
                __nv_bfloat16 h1 = __float2bfloat16_rn(w1);
                __nv_bfloat16 l0 = __float2bfloat16_rn(w0 - __bfloat162float(h0));
                __nv_bfloat16 l1 = __float2bfloat16_rn(w1 - __bfloat162float(h1));
                hp[d >> 1] = pack_bf2(h0, h1);
                lp[d >> 1] = pack_bf2(l0, l1);
            }
            // pair-interleaved 8-word groups: phys = {w0,w4,w1,w5},{w2,w6,w3,w7}
            uint4 H0 = make_uint4(hp[0], hp[4], hp[1], hp[5]);
            uint4 H1 = make_uint4(hp[2], hp[6], hp[3], hp[7]);
            uint4 L0 = make_uint4(lp[0], lp[4], lp[1], lp[5]);
            uint4 L1 = make_uint4(lp[2], lp[6], lp[3], lp[7]);
            if (is_x) {
                uint4* dst = (uint4*)(smem + AOFF(buf) + rowid * 96);
                dst[0] = H0; dst[1] = H1;   // k0: uh
                dst[2] = L0; dst[3] = L1;   // k1: ul
                dst[4] = H0; dst[5] = H1;   // k2: uh
                ((float*)(smem + CSOFF(buf)))[rowid] = -0.5f * LOG2E * s2;
            } else {
                // permuted slot: j64 bits (k,qc,m,e) -> slot (k,m,qc,e)
                const int j64 = rowid & 63;
                const int slot = (j64 & 0x30) | ((j64 & 2) << 2) |
                                 ((j64 & 0xC) >> 1) | (j64 & 1);
                const int brow = (rowid & 64) + slot;
                uint4* dst = (uint4*)(smem + BOFF(buf) + brow * 96);
                dst[0] = H0; dst[1] = H1;   // k0: vh
                dst[2] = H0; dst[3] = H1;   // k1: vh
                dst[4] = L0; dst[5] = L1;   // k2: vl
                ((float*)(smem + DSOFF(buf)))[rowid] =
                    -0.5f * LOG2E * s2 + SINV[16];
            }
        }

        // ---- prefetch next tile's rows (in flight over MMA+epilogue) ----
        if (tn < NT) {
            const int nbi = (tn >> 5) * 128, nbj = (tn & 31) * 128;
            const float4* rowp = is_x
                ? (const float4*)(x  + (size_t)(nbi + rowid) * 16)
                : (const float4*)(xx + (size_t)(nbj + rowid) * 16);
            ra = rowp[0]; rb = rowp[1]; rc = rowp[2]; rd = rowp[3];
        }
        __syncthreads();   // smem[buf] ready

        const char* Abase = smem + AOFF(buf);
        const char* Bbase = smem + BOFF(buf);
        const float* CSb  = (const float*)(smem + CSOFF(buf));

        // hoist a-fragments: LDS.64 x12 (3 ks x 2 mt x 2 rows)
        uint32_t af[3][2][4];
#pragma unroll
        for (int ks = 0; ks < 3; ks++) {
#pragma unroll
            for (int mt = 0; mt < 2; mt++) {
                const int r0 = wr + mt * 16 + qrow;
                uint2 p = *(const uint2*)(Abase + r0 * 96 + ks * 32 + qcol * 8);
                uint2 q = *(const uint2*)(Abase + (r0 + 8) * 96 + ks * 32 + qcol * 8);
                af[ks][mt][0] = p.x;  // a0 (kw)
                af[ks][mt][1] = q.x;  // a1
                af[ks][mt][2] = p.y;  // a2 (kw+4)
                af[ks][mt][3] = q.y;  // a3
            }
        }
        float ci[4];
#pragma unroll
        for (int q = 0; q < 4; q++) ci[q] = CSb[wr + qrow + 8 * q];

        // k-pair groups: 12 MMA -> 16 EX2 -> 4 STG.128 per group
#pragma unroll
        for (int k = 0; k < 4; k++) {
            float4 dj = *(const float4*)(smem + DSOFF(buf) +
                                         (wc + 16 * k + 4 * qcol) * 4);
            float a0[2][4], a1[2][4];   // nt=2k, nt=2k+1
#pragma unroll
            for (int mt = 0; mt < 2; mt++) {
                a0[mt][0] = ci[2 * mt] + dj.x;
                a0[mt][1] = ci[2 * mt] + dj.y;
                a0[mt][2] = ci[2 * mt + 1] + dj.x;
                a0[mt][3] = ci[2 * mt + 1] + dj.y;
                a1[mt][0] = ci[2 * mt] + dj.z;
                a1[mt][1] = ci[2 * mt] + dj.w;
                a1[mt][2] = ci[2 * mt + 1] + dj.z;
                a1[mt][3] = ci[2 * mt + 1] + dj.w;
            }
            const int jr0 = wc + 16 * k + qrow;      // nt=2k block
            const int jr1 = jr0 + 8;                 // nt=2k+1 block
#pragma unroll
            for (int ks = 0; ks < 3; ks++) {
                uint2 b0 = *(const uint2*)(Bbase + jr0 * 96 + ks * 32 + qcol * 8);
                uint2 b1 = *(const uint2*)(Bbase + jr1 * 96 + ks * 32 + qcol * 8);
                MMA16816(a0[0], af[ks][0], b0.x, b0.y);
                MMA16816(a0[1], af[ks][1], b0.x, b0.y);
                MMA16816(a1[0], af[ks][0], b1.x, b1.y);
                MMA16816(a1[1], af[ks][1], b1.x, b1.y);
            }
            const int col = bj0 + wc + 16 * k + 4 * qcol;
#pragma unroll
            for (int mt = 0; mt < 2; mt++) {
                float f0 = a0[mt][0], f1 = a0[mt][1];
                float f2 = a1[mt][0], f3 = a1[mt][1];
                float g0 = a0[mt][2], g1 = a0[mt][3];
                float g2 = a1[mt][2], g3 = a1[mt][3];
                asm("ex2.approx.ftz.f32 %0, %0;" : "+f"(f0));
                asm("ex2.approx.ftz.f32 %0, %0;" : "+f"(f1));
                asm("ex2.approx.ftz.f32 %0, %0;" : "+f"(f2));
                asm("ex2.approx.ftz.f32 %0, %0;" : "+f"(f3));
                asm("ex2.approx.ftz.f32 %0, %0;" : "+f"(g0));
                asm("ex2.approx.ftz.f32 %0, %0;" : "+f"(g1));
                asm("ex2.approx.ftz.f32 %0, %0;" : "+f"(g2));
                asm("ex2.approx.ftz.f32 %0, %0;" : "+f"(g3));
                const int r0g = bi0 + wr + mt * 16 + qrow;
                *(float4*)&out[(size_t)r0g * NPTS + col] =
                    make_float4(f0, f1, f2, f3);
                *(float4*)&out[(size_t)(r0g + 8) * NPTS + col] =
                    make_float4(g0, g1, g2, g3);
            }
        }

        t = tn;
        buf ^= 1;
    }
}

extern "C" void kernel_launch(void* const* d_in, const int* in_sizes, int n_in,
                              void* d_out, int out_size) {
    const float* x        = (const float*)d_in[0];
    const float* xx       = (const float*)d_in[1];
    const float* scale_ff = (const float*)d_in[2];
    const float* var_ff   = (const float*)d_in[3];
    float* out = (float*)d_out;

    int sms = 148;
    cudaDeviceGetAttribute(&sms, cudaDevAttrMultiProcessorCount, 0);
    int grid = 2 * sms;
    if (grid > NT) grid = NT;

    cudaFuncSetAttribute(rbf_mma_p, cudaFuncAttributeMaxDynamicSharedMemorySize,
                         SMEM_REQ);
    rbf_mma_p<<<grid, 256, SMEM_REQ>>>(x, xx, scale_ff, var_ff, out);
}